// round 3
// baseline (speedup 1.0000x reference)
#include <cuda_runtime.h>
#include <cuda_bf16.h>
#include <cstdint>

// Output pattern, shape [2, G*N*N] flattened row-major, FLOAT32 values:
//   half 0: out[g*N*N + i]     = float(i / N)   (row index)
//   half 1: out[H + g*N*N + i] = float(i % N)   (col index),  H = G*N*N
// Pure write-only stream; input VALUES never read. rel_err == exactly 1.0 in
// R1/R2 implies d_out is interpreted as float32 (int bit patterns ~= 0.0f),
// so we emit float values. N from shape algebra: out_size = 2*G*N*N.

__global__ void fa_vec_kernel(float* __restrict__ out,
                              unsigned N, unsigned NN, long long halfElems) {
    unsigned i4 = ((unsigned)blockIdx.x * blockDim.x + threadIdx.x) * 4u;
    if (i4 >= NN) return;
    unsigned r = i4 / N;           // row index (constant across the 4-group)
    unsigned c = i4 - r * N;       // col index of first element
    long long base = (long long)blockIdx.y * (long long)NN + (long long)i4;

    float rf = (float)r;
    float cf = (float)c;
    float4 rv = make_float4(rf, rf, rf, rf);
    float4 cv = make_float4(cf, cf + 1.0f, cf + 2.0f, cf + 3.0f);

    reinterpret_cast<float4*>(out + base)[0] = rv;
    reinterpret_cast<float4*>(out + halfElems + base)[0] = cv;
}

__global__ void fa_scalar_kernel(float* __restrict__ out,
                                 unsigned N, unsigned NN, long long halfElems) {
    unsigned i = (unsigned)blockIdx.x * blockDim.x + threadIdx.x;
    if (i >= NN) return;
    unsigned r = i / N;
    unsigned c = i - r * N;
    long long base = (long long)blockIdx.y * (long long)NN + (long long)i;
    out[base] = (float)r;
    out[halfElems + base] = (float)c;
}

extern "C" void kernel_launch(void* const* d_in, const int* in_sizes, int n_in,
                              void* d_out, int out_size) {
    (void)d_in;
    // Derive N: the input size s for which out_size == 2*G*s*s with integer
    // 1 <= G <= 4096. (Avoids depending on metadata input ordering.)
    long long N = 0, G = 0;
    for (int i = 0; i < n_in; i++) {
        long long s = (long long)in_sizes[i];
        if (s <= 0) continue;
        long long denom = 2LL * s * s;
        if (denom <= 0) continue;
        if ((long long)out_size % denom != 0) continue;
        long long g = (long long)out_size / denom;
        if (g >= 1 && g <= 4096) { N = s; G = g; break; }
    }
    if (N == 0) {
        N = (long long)in_sizes[2];
        long long denom = 2LL * N * N;
        G = (denom > 0 && (long long)out_size % denom == 0)
                ? (long long)out_size / denom : 1;
    }

    const long long NNll = N * N;
    const unsigned NN = (unsigned)NNll;
    const long long halfElems = G * NNll;
    float* out = (float*)d_out;
    const int threads = 256;

    if ((N % 4) == 0 && NNll <= 0xFFFFFFFFLL) {
        const unsigned elems4 = NN / 4u;
        unsigned gx = (elems4 + threads - 1) / threads;
        if (gx == 0) gx = 1;
        dim3 grid(gx, (unsigned)G, 1);
        fa_vec_kernel<<<grid, threads>>>(out, (unsigned)N, NN, halfElems);
    } else {
        unsigned gx = (unsigned)((NNll + threads - 1) / threads);
        if (gx == 0) gx = 1;
        dim3 grid(gx, (unsigned)G, 1);
        fa_scalar_kernel<<<grid, threads>>>(out, (unsigned)N, NN, halfElems);
    }
}